// round 1
// baseline (speedup 1.0000x reference)
#include <cuda_runtime.h>
#include <cstdint>

// MoE brain model: B=1M tokens, 8 experts (10->32->32->2), gate (10->64->8 softmax),
// refine (12->64->2). Strategy: weights resident in SMEM (55.9 KB), one thread per
// token, all layers computed with packed fp32x2 FMA (fma.rn.f32x2 -> FFMA2).

#define B_TOK  1048576
#define NEXP   8

typedef unsigned long long u64;

__device__ __forceinline__ u64 pk(float a, float b) {
    u64 r; asm("mov.b64 %0,{%1,%2};" : "=l"(r) : "f"(a), "f"(b)); return r;
}
__device__ __forceinline__ u64 pkdup(float a) { return pk(a, a); }
__device__ __forceinline__ void upk(u64 v, float& a, float& b) {
    asm("mov.b64 {%0,%1},%2;" : "=f"(a), "=f"(b) : "l"(v));
}
__device__ __forceinline__ u64 fma2(u64 a, u64 b, u64 c) {
    u64 d; asm("fma.rn.f32x2 %0,%1,%2,%3;" : "=l"(d) : "l"(a), "l"(b), "l"(c)); return d;
}
__device__ __forceinline__ u64 f2u(float2 v) { return pk(v.x, v.y); }

// SMEM layout (float offsets). All matrix bases 16B-aligned for LDS.128.
#define OW1   0       // 8*10*32 = 2560
#define OB1   2560    // 8*32    = 256
#define OW2   2816    // 8*32*32 = 8192
#define OB2   11008   // 256
#define OW3   11264   // 8*32*2  = 512
#define OB3   11776   // 16
#define OG1   11792   // 10*64   = 640
#define OGB1  12432   // 64
#define OG2   12496   // 64*8    = 512
#define OGB2  13008   // 8
#define OR1   13016   // 12*64   = 768
#define ORB1  13784   // 64
#define OR2   13848   // 64*2    = 128
#define ORB2  13976   // 2
#define SMEM_FLOATS 13978

extern __shared__ float sw[];

__global__ void __launch_bounds__(256)
moe_brain_kernel(const float* __restrict__ X,
                 const float* __restrict__ W1, const float* __restrict__ b1,
                 const float* __restrict__ W2, const float* __restrict__ b2,
                 const float* __restrict__ W3, const float* __restrict__ b3,
                 const float* __restrict__ G1, const float* __restrict__ gb1,
                 const float* __restrict__ G2, const float* __restrict__ gb2,
                 const float* __restrict__ R1, const float* __restrict__ rb1,
                 const float* __restrict__ R2, const float* __restrict__ rb2,
                 float* __restrict__ out)
{
    // ---- stage all weights into SMEM (broadcast-read later; conflict-free) ----
    {
        const int tid = threadIdx.x;
        for (int i = tid; i < 2560; i += 256) sw[OW1 + i]  = W1[i];
        for (int i = tid; i < 256;  i += 256) sw[OB1 + i]  = b1[i];
        for (int i = tid; i < 8192; i += 256) sw[OW2 + i]  = W2[i];
        for (int i = tid; i < 256;  i += 256) sw[OB2 + i]  = b2[i];
        for (int i = tid; i < 512;  i += 256) sw[OW3 + i]  = W3[i];
        for (int i = tid; i < 16;   i += 256) sw[OB3 + i]  = b3[i];
        for (int i = tid; i < 640;  i += 256) sw[OG1 + i]  = G1[i];
        for (int i = tid; i < 64;   i += 256) sw[OGB1 + i] = gb1[i];
        for (int i = tid; i < 512;  i += 256) sw[OG2 + i]  = G2[i];
        for (int i = tid; i < 8;    i += 256) sw[OGB2 + i] = gb2[i];
        for (int i = tid; i < 768;  i += 256) sw[OR1 + i]  = R1[i];
        for (int i = tid; i < 64;   i += 256) sw[ORB1 + i] = rb1[i];
        for (int i = tid; i < 128;  i += 256) sw[OR2 + i]  = R2[i];
        if (tid < 2) sw[ORB2 + tid] = rb2[tid];
    }
    __syncthreads();

    const int t = blockIdx.x * 256 + threadIdx.x;
    if (t >= B_TOK) return;

    // ---- load x[10] (row stride 40B, 8B-aligned -> 5x LDG.64, coalesced) ----
    float x[10];
    {
        const float2* xp = reinterpret_cast<const float2*>(X + (size_t)t * 10);
        #pragma unroll
        for (int i = 0; i < 5; i++) { float2 v = xp[i]; x[2*i] = v.x; x[2*i+1] = v.y; }
    }

    // ---- gate layer 1: 10 -> 64, relu ----
    float gv[64];
    {
        u64 acc[32];
        const float2* bp = (const float2*)(sw + OGB1);
        #pragma unroll
        for (int j = 0; j < 32; j++) acc[j] = f2u(bp[j]);
        #pragma unroll
        for (int k = 0; k < 10; k++) {
            u64 a = pkdup(x[k]);
            const float4* wr = (const float4*)(sw + OG1 + k * 64);
            #pragma unroll
            for (int j = 0; j < 16; j++) {
                float4 w = wr[j];
                acc[2*j]   = fma2(a, pk(w.x, w.y), acc[2*j]);
                acc[2*j+1] = fma2(a, pk(w.z, w.w), acc[2*j+1]);
            }
        }
        #pragma unroll
        for (int j = 0; j < 32; j++) {
            float lo, hi; upk(acc[j], lo, hi);
            gv[2*j] = fmaxf(lo, 0.f); gv[2*j+1] = fmaxf(hi, 0.f);
        }
    }

    // ---- gate layer 2: 64 -> 8, softmax (kept unnormalized; divide at fuse) ----
    float wexp[8], wsum;
    {
        u64 acc[4];
        const float2* bp = (const float2*)(sw + OGB2);
        #pragma unroll
        for (int j = 0; j < 4; j++) acc[j] = f2u(bp[j]);
        #pragma unroll
        for (int k = 0; k < 64; k++) {
            u64 a = pkdup(gv[k]);
            const float4* wr = (const float4*)(sw + OG2 + k * 8);
            #pragma unroll
            for (int j = 0; j < 2; j++) {
                float4 w = wr[j];
                acc[2*j]   = fma2(a, pk(w.x, w.y), acc[2*j]);
                acc[2*j+1] = fma2(a, pk(w.z, w.w), acc[2*j+1]);
            }
        }
        float l[8];
        #pragma unroll
        for (int j = 0; j < 4; j++) upk(acc[j], l[2*j], l[2*j+1]);
        float m = l[0];
        #pragma unroll
        for (int i = 1; i < 8; i++) m = fmaxf(m, l[i]);
        wsum = 0.f;
        #pragma unroll
        for (int i = 0; i < 8; i++) { wexp[i] = __expf(l[i] - m); wsum += wexp[i]; }
    }

    // ---- experts: 8 x (10->32 relu, 32->32 relu, 32->2 tanh), weighted fuse ----
    u64 fused = 0ull;  // packed (0.f, 0.f)
    #pragma unroll 1   // keep I-footprint bounded; inner layers fully unrolled
    for (int e = 0; e < NEXP; e++) {
        float h1v[32];
        {
            u64 acc[16];
            const float2* bp = (const float2*)(sw + OB1 + e * 32);
            #pragma unroll
            for (int j = 0; j < 16; j++) acc[j] = f2u(bp[j]);
            #pragma unroll
            for (int k = 0; k < 10; k++) {
                u64 a = pkdup(x[k]);
                const float4* wr = (const float4*)(sw + OW1 + e * 320 + k * 32);
                #pragma unroll
                for (int j = 0; j < 8; j++) {
                    float4 w = wr[j];
                    acc[2*j]   = fma2(a, pk(w.x, w.y), acc[2*j]);
                    acc[2*j+1] = fma2(a, pk(w.z, w.w), acc[2*j+1]);
                }
            }
            #pragma unroll
            for (int j = 0; j < 16; j++) {
                float lo, hi; upk(acc[j], lo, hi);
                h1v[2*j] = fmaxf(lo, 0.f); h1v[2*j+1] = fmaxf(hi, 0.f);
            }
        }
        float h2v[32];
        {
            u64 acc[16];
            const float2* bp = (const float2*)(sw + OB2 + e * 32);
            #pragma unroll
            for (int j = 0; j < 16; j++) acc[j] = f2u(bp[j]);
            #pragma unroll
            for (int k = 0; k < 32; k++) {
                u64 a = pkdup(h1v[k]);
                const float4* wr = (const float4*)(sw + OW2 + e * 1024 + k * 32);
                #pragma unroll
                for (int j = 0; j < 8; j++) {
                    float4 w = wr[j];
                    acc[2*j]   = fma2(a, pk(w.x, w.y), acc[2*j]);
                    acc[2*j+1] = fma2(a, pk(w.z, w.w), acc[2*j+1]);
                }
            }
            #pragma unroll
            for (int j = 0; j < 16; j++) {
                float lo, hi; upk(acc[j], lo, hi);
                h2v[2*j] = fmaxf(lo, 0.f); h2v[2*j+1] = fmaxf(hi, 0.f);
            }
        }
        // out layer 32 -> 2, tanh
        u64 oacc = f2u(((const float2*)(sw + OB3))[e]);
        const float2* wr3 = (const float2*)(sw + OW3 + e * 64);
        #pragma unroll
        for (int k = 0; k < 32; k++)
            oacc = fma2(pkdup(h2v[k]), f2u(wr3[k]), oacc);
        float o0, o1; upk(oacc, o0, o1);
        o0 = tanhf(o0); o1 = tanhf(o1);
        fused = fma2(pkdup(wexp[e]), pk(o0, o1), fused);
    }
    float f0, f1; upk(fused, f0, f1);
    const float inv = 1.0f / wsum;
    f0 *= inv; f1 *= inv;

    // ---- refine: concat([f0,f1], x) (12) -> 64 relu -> 2 tanh ----
    float rin[12];
    rin[0] = f0; rin[1] = f1;
    #pragma unroll
    for (int i = 0; i < 10; i++) rin[2 + i] = x[i];

    float rv[64];
    {
        u64 acc[32];
        const float2* bp = (const float2*)(sw + ORB1);
        #pragma unroll
        for (int j = 0; j < 32; j++) acc[j] = f2u(bp[j]);
        #pragma unroll
        for (int k = 0; k < 12; k++) {
            u64 a = pkdup(rin[k]);
            const float4* wr = (const float4*)(sw + OR1 + k * 64);
            #pragma unroll
            for (int j = 0; j < 16; j++) {
                float4 w = wr[j];
                acc[2*j]   = fma2(a, pk(w.x, w.y), acc[2*j]);
                acc[2*j+1] = fma2(a, pk(w.z, w.w), acc[2*j+1]);
            }
        }
        #pragma unroll
        for (int j = 0; j < 32; j++) {
            float lo, hi; upk(acc[j], lo, hi);
            rv[2*j] = fmaxf(lo, 0.f); rv[2*j+1] = fmaxf(hi, 0.f);
        }
    }
    u64 acc2 = f2u(*(const float2*)(sw + ORB2));
    const float2* r2 = (const float2*)(sw + OR2);
    #pragma unroll
    for (int k = 0; k < 64; k++)
        acc2 = fma2(pkdup(rv[k]), f2u(r2[k]), acc2);
    float y0, y1; upk(acc2, y0, y1);
    y0 = tanhf(y0); y1 = tanhf(y1);

    reinterpret_cast<float2*>(out)[t] = make_float2(y0, y1);
}

extern "C" void kernel_launch(void* const* d_in, const int* in_sizes, int n_in,
                              void* d_out, int out_size)
{
    (void)in_sizes; (void)n_in; (void)out_size;
    const float* X   = (const float*)d_in[0];
    const float* W1  = (const float*)d_in[1];
    const float* b1  = (const float*)d_in[2];
    const float* W2  = (const float*)d_in[3];
    const float* b2  = (const float*)d_in[4];
    const float* W3  = (const float*)d_in[5];
    const float* b3  = (const float*)d_in[6];
    const float* G1  = (const float*)d_in[7];
    const float* gb1 = (const float*)d_in[8];
    const float* G2  = (const float*)d_in[9];
    const float* gb2 = (const float*)d_in[10];
    const float* R1  = (const float*)d_in[11];
    const float* rb1 = (const float*)d_in[12];
    const float* R2  = (const float*)d_in[13];
    const float* rb2 = (const float*)d_in[14];

    const size_t smem = SMEM_FLOATS * sizeof(float);
    cudaFuncSetAttribute(moe_brain_kernel,
                         cudaFuncAttributeMaxDynamicSharedMemorySize, (int)smem);

    moe_brain_kernel<<<B_TOK / 256, 256, smem>>>(
        X, W1, b1, W2, b2, W3, b3, G1, gb1, G2, gb2, R1, rb1, R2, rb2,
        (float*)d_out);
}

// round 2
// speedup vs baseline: 1.5605x; 1.5605x over previous
#include <cuda_runtime.h>
#include <cstdint>

// MoE brain model, round 2: 2 tokens per thread to halve LDS-per-FMA.
// Weights in SMEM (55.9 KB), packed fp32x2 FMA (fma.rn.f32x2 -> FFMA2),
// layer-pair fusion (chunked) to bound register pressure.

#define B_TOK  1048576
#define NEXP   8

typedef unsigned long long u64;

__device__ __forceinline__ u64 pk(float a, float b) {
    u64 r; asm("mov.b64 %0,{%1,%2};" : "=l"(r) : "f"(a), "f"(b)); return r;
}
__device__ __forceinline__ u64 pkdup(float a) { return pk(a, a); }
__device__ __forceinline__ void upk(u64 v, float& a, float& b) {
    asm("mov.b64 {%0,%1},%2;" : "=f"(a), "=f"(b) : "l"(v));
}
__device__ __forceinline__ u64 fma2(u64 a, u64 b, u64 c) {
    u64 d; asm("fma.rn.f32x2 %0,%1,%2,%3;" : "=l"(d) : "l"(a), "l"(b), "l"(c)); return d;
}
__device__ __forceinline__ u64 f2u(float2 v) { return pk(v.x, v.y); }

// SMEM layout (float offsets). All matrix bases 16B-aligned.
#define OW1   0       // 8*10*32 = 2560
#define OB1   2560    // 8*32    = 256
#define OW2   2816    // 8*32*32 = 8192
#define OB2   11008   // 256
#define OW3   11264   // 8*32*2  = 512
#define OB3   11776   // 16
#define OG1   11792   // 10*64   = 640
#define OGB1  12432   // 64
#define OG2   12496   // 64*8    = 512
#define OGB2  13008   // 8
#define OR1   13016   // 12*64   = 768
#define ORB1  13784   // 64
#define OR2   13848   // 64*2    = 128
#define ORB2  13976   // 2
#define SMEM_FLOATS 13978

extern __shared__ float sw[];

__global__ void __launch_bounds__(128, 3)
moe_brain_kernel(const float* __restrict__ X,
                 const float* __restrict__ W1, const float* __restrict__ b1,
                 const float* __restrict__ W2, const float* __restrict__ b2,
                 const float* __restrict__ W3, const float* __restrict__ b3,
                 const float* __restrict__ G1, const float* __restrict__ gb1,
                 const float* __restrict__ G2, const float* __restrict__ gb2,
                 const float* __restrict__ R1, const float* __restrict__ rb1,
                 const float* __restrict__ R2, const float* __restrict__ rb2,
                 float* __restrict__ out)
{
    // ---- stage all weights into SMEM ----
    {
        const int tid = threadIdx.x;
        for (int i = tid; i < 2560; i += 128) sw[OW1 + i]  = W1[i];
        for (int i = tid; i < 256;  i += 128) sw[OB1 + i]  = b1[i];
        for (int i = tid; i < 8192; i += 128) sw[OW2 + i]  = W2[i];
        for (int i = tid; i < 256;  i += 128) sw[OB2 + i]  = b2[i];
        for (int i = tid; i < 512;  i += 128) sw[OW3 + i]  = W3[i];
        for (int i = tid; i < 16;   i += 128) sw[OB3 + i]  = b3[i];
        for (int i = tid; i < 640;  i += 128) sw[OG1 + i]  = G1[i];
        for (int i = tid; i < 64;   i += 128) sw[OGB1 + i] = gb1[i];
        for (int i = tid; i < 512;  i += 128) sw[OG2 + i]  = G2[i];
        for (int i = tid; i < 8;    i += 128) sw[OGB2 + i] = gb2[i];
        for (int i = tid; i < 768;  i += 128) sw[OR1 + i]  = R1[i];
        for (int i = tid; i < 64;   i += 128) sw[ORB1 + i] = rb1[i];
        for (int i = tid; i < 128;  i += 128) sw[OR2 + i]  = R2[i];
        if (tid < 2) sw[ORB2 + tid] = rb2[tid];
    }
    __syncthreads();

    // 2 tokens per thread: block covers 256 tokens, coalesced within each half.
    const int t0 = blockIdx.x * 256 + threadIdx.x;
    const int t1 = t0 + 128;

    float x[2][10];
    {
        const float2* xp0 = reinterpret_cast<const float2*>(X + (size_t)t0 * 10);
        const float2* xp1 = reinterpret_cast<const float2*>(X + (size_t)t1 * 10);
        #pragma unroll
        for (int i = 0; i < 5; i++) {
            float2 v0 = xp0[i]; x[0][2*i] = v0.x; x[0][2*i+1] = v0.y;
            float2 v1 = xp1[i]; x[1][2*i] = v1.x; x[1][2*i+1] = v1.y;
        }
    }

    // ---- gate: fused (10->64 relu) -> (64->8), chunked 16 hidden at a time ----
    float wexp[2][8], wsum[2];
    {
        u64 l2a[2][4];
        const float2* gb2p = (const float2*)(sw + OGB2);
        #pragma unroll
        for (int j = 0; j < 4; j++) { u64 v = f2u(gb2p[j]); l2a[0][j] = v; l2a[1][j] = v; }

        #pragma unroll 1
        for (int c = 0; c < 4; c++) {
            u64 acc[2][8];
            const float2* bp = (const float2*)(sw + OGB1 + c * 16);
            #pragma unroll
            for (int j = 0; j < 8; j++) { u64 v = f2u(bp[j]); acc[0][j] = v; acc[1][j] = v; }
            #pragma unroll
            for (int k = 0; k < 10; k++) {
                u64 m0 = pkdup(x[0][k]), m1 = pkdup(x[1][k]);
                const float4* wr = (const float4*)(sw + OG1 + k * 64 + c * 16);
                #pragma unroll
                for (int j = 0; j < 4; j++) {
                    float4 w = wr[j];
                    u64 wl = pk(w.x, w.y), wh = pk(w.z, w.w);
                    acc[0][2*j]   = fma2(m0, wl, acc[0][2*j]);
                    acc[0][2*j+1] = fma2(m0, wh, acc[0][2*j+1]);
                    acc[1][2*j]   = fma2(m1, wl, acc[1][2*j]);
                    acc[1][2*j+1] = fma2(m1, wh, acc[1][2*j+1]);
                }
            }
            // relu + fold into gate layer2
            #pragma unroll
            for (int j = 0; j < 8; j++) {
                const float4* g2r = (const float4*)(sw + OG2 + (c * 16 + 2 * j) * 8);
                float4 ra0 = g2r[0], ra1 = g2r[1];   // row for even hidden
                float4 rb0 = g2r[2], rb1_ = g2r[3];  // row for odd hidden
                u64 a0l = pk(ra0.x, ra0.y), a0h = pk(ra0.z, ra0.w);
                u64 a1l = pk(ra1.x, ra1.y), a1h = pk(ra1.z, ra1.w);
                u64 b0l = pk(rb0.x, rb0.y), b0h = pk(rb0.z, rb0.w);
                u64 b1l = pk(rb1_.x, rb1_.y), b1h = pk(rb1_.z, rb1_.w);
                #pragma unroll
                for (int tt = 0; tt < 2; tt++) {
                    float p, q; upk(acc[tt][j], p, q);
                    p = fmaxf(p, 0.f); q = fmaxf(q, 0.f);
                    u64 mp = pkdup(p), mq = pkdup(q);
                    l2a[tt][0] = fma2(mp, a0l, l2a[tt][0]);
                    l2a[tt][1] = fma2(mp, a0h, l2a[tt][1]);
                    l2a[tt][2] = fma2(mp, a1l, l2a[tt][2]);
                    l2a[tt][3] = fma2(mp, a1h, l2a[tt][3]);
                    l2a[tt][0] = fma2(mq, b0l, l2a[tt][0]);
                    l2a[tt][1] = fma2(mq, b0h, l2a[tt][1]);
                    l2a[tt][2] = fma2(mq, b1l, l2a[tt][2]);
                    l2a[tt][3] = fma2(mq, b1h, l2a[tt][3]);
                }
            }
        }
        #pragma unroll
        for (int tt = 0; tt < 2; tt++) {
            float l[8];
            #pragma unroll
            for (int j = 0; j < 4; j++) upk(l2a[tt][j], l[2*j], l[2*j+1]);
            float m = l[0];
            #pragma unroll
            for (int i = 1; i < 8; i++) m = fmaxf(m, l[i]);
            float s = 0.f;
            #pragma unroll
            for (int i = 0; i < 8; i++) { wexp[tt][i] = __expf(l[i] - m); s += wexp[tt][i]; }
            wsum[tt] = s;
        }
    }

    // ---- experts: 8 x (10->32 relu, fused 32->32 relu ->2), weighted fuse ----
    u64 fused[2] = {0ull, 0ull};
    #pragma unroll 1
    for (int e = 0; e < NEXP; e++) {
        float h1[2][32];
        {
            u64 acc[2][16];
            const float2* bp = (const float2*)(sw + OB1 + e * 32);
            #pragma unroll
            for (int j = 0; j < 16; j++) { u64 v = f2u(bp[j]); acc[0][j] = v; acc[1][j] = v; }
            #pragma unroll
            for (int k = 0; k < 10; k++) {
                u64 m0 = pkdup(x[0][k]), m1 = pkdup(x[1][k]);
                const float4* wr = (const float4*)(sw + OW1 + e * 320 + k * 32);
                #pragma unroll
                for (int j = 0; j < 8; j++) {
                    float4 w = wr[j];
                    u64 wl = pk(w.x, w.y), wh = pk(w.z, w.w);
                    acc[0][2*j]   = fma2(m0, wl, acc[0][2*j]);
                    acc[0][2*j+1] = fma2(m0, wh, acc[0][2*j+1]);
                    acc[1][2*j]   = fma2(m1, wl, acc[1][2*j]);
                    acc[1][2*j+1] = fma2(m1, wh, acc[1][2*j+1]);
                }
            }
            #pragma unroll
            for (int j = 0; j < 16; j++) {
                float lo, hi;
                upk(acc[0][j], lo, hi);
                h1[0][2*j] = fmaxf(lo, 0.f); h1[0][2*j+1] = fmaxf(hi, 0.f);
                upk(acc[1][j], lo, hi);
                h1[1][2*j] = fmaxf(lo, 0.f); h1[1][2*j+1] = fmaxf(hi, 0.f);
            }
        }
        // fused layer2 (32->32 relu) + layer3 (32->2), chunked 8 h2 at a time
        u64 oacc[2];
        { u64 v = f2u(((const float2*)(sw + OB3))[e]); oacc[0] = v; oacc[1] = v; }
        #pragma unroll 1
        for (int c = 0; c < 4; c++) {
            u64 acc[2][4];
            const float2* bp = (const float2*)(sw + OB2 + e * 32 + c * 8);
            #pragma unroll
            for (int j = 0; j < 4; j++) { u64 v = f2u(bp[j]); acc[0][j] = v; acc[1][j] = v; }
            #pragma unroll
            for (int k = 0; k < 32; k++) {
                u64 m0 = pkdup(h1[0][k]), m1 = pkdup(h1[1][k]);
                const float4* wr = (const float4*)(sw + OW2 + e * 1024 + k * 32 + c * 8);
                float4 wa = wr[0], wb = wr[1];
                u64 w0 = pk(wa.x, wa.y), w1 = pk(wa.z, wa.w);
                u64 w2 = pk(wb.x, wb.y), w3 = pk(wb.z, wb.w);
                acc[0][0] = fma2(m0, w0, acc[0][0]);
                acc[0][1] = fma2(m0, w1, acc[0][1]);
                acc[0][2] = fma2(m0, w2, acc[0][2]);
                acc[0][3] = fma2(m0, w3, acc[0][3]);
                acc[1][0] = fma2(m1, w0, acc[1][0]);
                acc[1][1] = fma2(m1, w1, acc[1][1]);
                acc[1][2] = fma2(m1, w2, acc[1][2]);
                acc[1][3] = fma2(m1, w3, acc[1][3]);
            }
            // relu + fold into 2-wide output
            #pragma unroll
            for (int j = 0; j < 4; j++) {
                const float2* w3r = (const float2*)(sw + OW3 + e * 64 + (c * 8 + 2 * j) * 2);
                u64 we = f2u(w3r[0]), wo = f2u(w3r[1]);
                #pragma unroll
                for (int tt = 0; tt < 2; tt++) {
                    float p, q; upk(acc[tt][j], p, q);
                    p = fmaxf(p, 0.f); q = fmaxf(q, 0.f);
                    oacc[tt] = fma2(pkdup(p), we, oacc[tt]);
                    oacc[tt] = fma2(pkdup(q), wo, oacc[tt]);
                }
            }
        }
        #pragma unroll
        for (int tt = 0; tt < 2; tt++) {
            float o0, o1; upk(oacc[tt], o0, o1);
            o0 = tanhf(o0); o1 = tanhf(o1);
            fused[tt] = fma2(pkdup(wexp[tt][e]), pk(o0, o1), fused[tt]);
        }
    }

    // ---- refine: concat -> (12->64 relu) fused with (64->2), chunked ----
    float rin[2][12];
    #pragma unroll
    for (int tt = 0; tt < 2; tt++) {
        float f0, f1; upk(fused[tt], f0, f1);
        const float inv = 1.0f / wsum[tt];
        rin[tt][0] = f0 * inv; rin[tt][1] = f1 * inv;
        #pragma unroll
        for (int i = 0; i < 10; i++) rin[tt][2 + i] = x[tt][i];
    }

    u64 racc[2];
    { u64 v = f2u(*(const float2*)(sw + ORB2)); racc[0] = v; racc[1] = v; }
    #pragma unroll 1
    for (int c = 0; c < 4; c++) {
        u64 acc[2][8];
        const float2* bp = (const float2*)(sw + ORB1 + c * 16);
        #pragma unroll
        for (int j = 0; j < 8; j++) { u64 v = f2u(bp[j]); acc[0][j] = v; acc[1][j] = v; }
        #pragma unroll
        for (int k = 0; k < 12; k++) {
            u64 m0 = pkdup(rin[0][k]), m1 = pkdup(rin[1][k]);
            const float4* wr = (const float4*)(sw + OR1 + k * 64 + c * 16);
            #pragma unroll
            for (int j = 0; j < 4; j++) {
                float4 w = wr[j];
                u64 wl = pk(w.x, w.y), wh = pk(w.z, w.w);
                acc[0][2*j]   = fma2(m0, wl, acc[0][2*j]);
                acc[0][2*j+1] = fma2(m0, wh, acc[0][2*j+1]);
                acc[1][2*j]   = fma2(m1, wl, acc[1][2*j]);
                acc[1][2*j+1] = fma2(m1, wh, acc[1][2*j+1]);
            }
        }
        #pragma unroll
        for (int j = 0; j < 8; j++) {
            const float2* r2 = (const float2*)(sw + OR2 + (c * 16 + 2 * j) * 2);
            u64 we = f2u(r2[0]), wo = f2u(r2[1]);
            #pragma unroll
            for (int tt = 0; tt < 2; tt++) {
                float p, q; upk(acc[tt][j], p, q);
                p = fmaxf(p, 0.f); q = fmaxf(q, 0.f);
                racc[tt] = fma2(pkdup(p), we, racc[tt]);
                racc[tt] = fma2(pkdup(q), wo, racc[tt]);
            }
        }
    }

    {
        float y0, y1; upk(racc[0], y0, y1);
        reinterpret_cast<float2*>(out)[t0] = make_float2(tanhf(y0), tanhf(y1));
        upk(racc[1], y0, y1);
        reinterpret_cast<float2*>(out)[t1] = make_float2(tanhf(y0), tanhf(y1));
    }
}

extern "C" void kernel_launch(void* const* d_in, const int* in_sizes, int n_in,
                              void* d_out, int out_size)
{
    (void)in_sizes; (void)n_in; (void)out_size;
    const float* X   = (const float*)d_in[0];
    const float* W1  = (const float*)d_in[1];
    const float* b1  = (const float*)d_in[2];
    const float* W2  = (const float*)d_in[3];
    const float* b2  = (const float*)d_in[4];
    const float* W3  = (const float*)d_in[5];
    const float* b3  = (const float*)d_in[6];
    const float* G1  = (const float*)d_in[7];
    const float* gb1 = (const float*)d_in[8];
    const float* G2  = (const float*)d_in[9];
    const float* gb2 = (const float*)d_in[10];
    const float* R1  = (const float*)d_in[11];
    const float* rb1 = (const float*)d_in[12];
    const float* R2  = (const float*)d_in[13];
    const float* rb2 = (const float*)d_in[14];

    const size_t smem = SMEM_FLOATS * sizeof(float);
    cudaFuncSetAttribute(moe_brain_kernel,
                         cudaFuncAttributeMaxDynamicSharedMemorySize, (int)smem);

    moe_brain_kernel<<<B_TOK / 256, 128, smem>>>(
        X, W1, b1, W2, b2, W3, b3, G1, gb1, G2, gb2, R1, rb1, R2, rb2,
        (float*)d_out);
}